// round 11
// baseline (speedup 1.0000x reference)
#include <cuda_runtime.h>

// Problem constants: x[16,128,8192] f32, weights1[128,128,2048] f32,
// output [16,128,4097] f32.
#define B_     16
#define CIN_   128
#define COUT_  128
#define N_     8192
#define MODES_ 2048
#define LOUT_  4097

#define NROWS  (B_ * CIN_)                  // 2048 blocks
#define OUT4_PER_BLK 1024                   // 4096 floats zeroed per block

// Row sums S[b,i] = sum_n x[b,i,n]
__device__ float g_S[NROWS];
// Gathered first-mode weights: g_W[i*COUT_ + o] = w[i,o,0]
__device__ float g_W[CIN_ * COUT_];
// Monotonic ticket counter (never reset; wrap-safe unsigned math).
__device__ unsigned g_ctr = 0u;

__device__ __forceinline__ unsigned ticket_release(unsigned* p) {
    unsigned t;
    asm volatile("atom.add.release.gpu.global.u32 %0, [%1], 1;"
                 : "=r"(t) : "l"(p) : "memory");
    return t;
}
__device__ __forceinline__ unsigned load_acquire(unsigned* p) {
    unsigned v;
    asm volatile("ld.acquire.gpu.global.u32 %0, [%1];"
                 : "=r"(v) : "l"(p) : "memory");
    return v;
}
// unpack u64 -> two floats
__device__ __forceinline__ float2 u64_as_f2(unsigned long long v) {
    float2 f;
    asm("mov.b64 {%0,%1}, %2;" : "=f"(f.x), "=f"(f.y) : "l"(v));
    return f;
}
// 32-byte evict-last load (sm_103 requires .v4.b64/.v8.b32 for this hint);
// returns the sum of the 8 packed floats.
__device__ __forceinline__ float ld32B_el_sum(const void* p) {
    unsigned long long r0, r1, r2, r3;
    asm("ld.global.L2::evict_last.v4.b64 {%0,%1,%2,%3}, [%4];"
        : "=l"(r0), "=l"(r1), "=l"(r2), "=l"(r3) : "l"(p));
    float2 f0 = u64_as_f2(r0), f1 = u64_as_f2(r1);
    float2 f2 = u64_as_f2(r2), f3 = u64_as_f2(r3);
    return ((f0.x + f0.y) + (f1.x + f1.y)) + ((f2.x + f2.y) + (f3.x + f3.y));
}

// ---------------------------------------------------------------------------
// Single fused kernel. Block `row` = (b,i):
//   (a) zero its 4096-float slice of out with EVICT-FIRST stores, skipping
//       the one head element in this slice (local float offset = row).
//   (b) blocks 0..127 gather w[i,o,0] -> g_W (one threadfence, 128 blocks).
//   (c) row-sum of x with 32B EVICT-LAST loads -> g_S[row].
//   (d) release-ticket; last B_ arrivals compute the head.
// ---------------------------------------------------------------------------
__global__ void __launch_bounds__(256) fused_kernel(const float* __restrict__ x,
                                                    const float* __restrict__ w,
                                                    float* __restrict__ out) {
    const int row = blockIdx.x;            // 0..2047
    const int tid = threadIdx.x;

    // (a) zero slice with streaming stores, skipping head element
    {
        const int sf4 = row >> 2;          // special local float4 index (<512)
        const int sc  = row & 3;           // component head will write
        float4 z = make_float4(0.0f, 0.0f, 0.0f, 0.0f);
        float4* o4 = reinterpret_cast<float4*>(out) + (size_t)row * OUT4_PER_BLK;
        #pragma unroll
        for (int j = 0; j < OUT4_PER_BLK / 256; j++) {
            const int idx = tid + j * 256;
            if (idx != sf4) {
                __stcs(&o4[idx], z);
            } else {
                float* os = reinterpret_cast<float*>(o4 + idx);
                #pragma unroll
                for (int c = 0; c < 4; c++)
                    if (c != sc) __stcs(&os[c], 0.0f);
            }
        }
    }

    // (b) gather weight column 0 (blocks 0..127 only)
    if (row < CIN_) {
        if (tid < COUT_)
            g_W[row * COUT_ + tid] = __ldg(&w[(size_t)(row * COUT_ + tid) * MODES_]);
        __threadfence();   // orders g_W before this block's ticket
    }

    // (c) row sum — 32B evict-last loads: persist x in L2 across replays.
    // Row = 8192 floats = 1024 x 32B chunks; 256 threads -> 4 chunks each.
    const char* xr = reinterpret_cast<const char*>(x) + (size_t)row * (N_ * 4);
    float sum = 0.0f;
    #pragma unroll
    for (int j = 0; j < 4; j++) {
        sum += ld32B_el_sum(xr + (size_t)(tid + j * 256) * 32);
    }
    #pragma unroll
    for (int off = 16; off > 0; off >>= 1)
        sum += __shfl_xor_sync(0xffffffffu, sum, off);

    __shared__ float wsum[8];
    const int lane = tid & 31;
    const int wid  = tid >> 5;
    if (lane == 0) wsum[wid] = sum;
    __syncthreads();
    if (wid == 0) {
        float s = (lane < 8) ? wsum[lane] : 0.0f;
        #pragma unroll
        for (int off = 4; off > 0; off >>= 1)
            s += __shfl_xor_sync(0xffffffffu, s, off);
        if (lane == 0) g_S[row] = s;     // written by tid0
    }
    __syncthreads();

    // (d) release ticket by tid0
    __shared__ unsigned ts;
    if (tid == 0) ts = ticket_release(&g_ctr);
    __syncthreads();
    const unsigned t    = ts;
    const unsigned r    = t & (unsigned)(NROWS - 1);
    const unsigned base = t - r;

    if (r >= (unsigned)(NROWS - B_)) {    // last 16 arrivals -> head work
        if (tid == 0) {
            while (load_acquire(&g_ctr) - base < (unsigned)NROWS) { }
        }
        __syncthreads();

        const int b = (int)(r - (unsigned)(NROWS - B_));   // 0..15

        __shared__ float Ssh[CIN_];
        __shared__ float part[256];
        if (tid < CIN_) Ssh[tid] = g_S[b * CIN_ + tid];
        __syncthreads();

        const int o    = tid & (COUT_ - 1);
        const int half = tid >> 7;
        float acc = 0.0f;
        #pragma unroll 8
        for (int i = half * (CIN_ / 2); i < (half + 1) * (CIN_ / 2); i++)
            acc += Ssh[i] * g_W[i * COUT_ + o];
        part[tid] = acc;
        __syncthreads();

        if (tid < COUT_) {
            float v = (part[tid] + part[tid + COUT_]) * (1.0f / 4097.0f);
            out[(size_t)(b * COUT_ + tid) * LOUT_] = v;
        }
    }
}

// ---------------------------------------------------------------------------
extern "C" void kernel_launch(void* const* d_in, const int* in_sizes, int n_in,
                              void* d_out, int out_size) {
    const float* x = (const float*)d_in[0];
    const float* w = (const float*)d_in[1];
    float* out = (float*)d_out;

    fused_kernel<<<NROWS, 256>>>(x, w, out);
}

// round 12
// speedup vs baseline: 1.0846x; 1.0846x over previous
#include <cuda_runtime.h>

// Problem constants: x[16,128,8192] f32, weights1[128,128,2048] f32,
// output [16,128,4097] f32.
#define B_     16
#define CIN_   128
#define COUT_  128
#define N_     8192
#define MODES_ 2048
#define LOUT_  4097

#define NROWS   (B_ * CIN_)                 // 2048 reader blocks
#define NBLK    (2 * NROWS)                 // 4096 total (power of 2)
#define OUT4    ((B_ * COUT_ * LOUT_) / 4)  // 2097664 float4
#define W4_MAIN 1024                        // float4 per writer block
#define W4_REM  (OUT4 - NROWS * W4_MAIN)    // 512 remainder float4

// Row sums S[b,i] = sum_n x[b,i,n]
__device__ float g_S[NROWS];
// Gathered first-mode weights: g_W[i*COUT_ + o] = w[i,o,0]
__device__ float g_W[CIN_ * COUT_];
// Monotonic ticket counter (never reset; NBLK is a power of 2 -> wrap-safe).
__device__ unsigned g_ctr = 0u;

__device__ __forceinline__ unsigned ticket_release(unsigned* p) {
    unsigned t;
    asm volatile("atom.add.release.gpu.global.u32 %0, [%1], 1;"
                 : "=r"(t) : "l"(p) : "memory");
    return t;
}
__device__ __forceinline__ unsigned load_acquire(unsigned* p) {
    unsigned v;
    asm volatile("ld.acquire.gpu.global.u32 %0, [%1];"
                 : "=r"(v) : "l"(p) : "memory");
    return v;
}

// ---------------------------------------------------------------------------
// Single kernel, block-specialized:
//   even blockIdx -> READER: pure-load row sum of x row (b>>1) -> g_S.
//   odd  blockIdx -> WRITER: pure evict-first zero stores of a 16KB out slice
//                    (writer 0 also covers the 512-float4 remainder).
//   Every block then takes a release ticket; the last 16 arrivals spin
//   (acquire) and compute out[b,o,0] = (1/4097) * sum_i S[b,i]*W[i,o].
//   Release/acquire ordering makes writer zeros happen-before head stores,
//   so no zero-skip logic is needed anywhere.
// ---------------------------------------------------------------------------
__global__ void __launch_bounds__(256) fused_kernel(const float* __restrict__ x,
                                                    const float* __restrict__ w,
                                                    float* __restrict__ out) {
    const int blk = blockIdx.x;            // 0..4095
    const int tid = threadIdx.x;
    const int idx2 = blk >> 1;             // reader row / writer index

    if ((blk & 1) == 0) {
        // ------------------- READER: row sum, pure loads -------------------
        const int row = idx2;              // 0..2047

        // gather weight column 0 (first 128 readers only): 1 load/thread
        if (row < CIN_ && tid < COUT_)
            g_W[row * COUT_ + tid] = __ldg(&w[(size_t)(row * COUT_ + tid) * MODES_]);

        const float4* __restrict__ xr =
            reinterpret_cast<const float4*>(x) + (size_t)row * (N_ / 4);
        float sum = 0.0f;
        #pragma unroll
        for (int j = 0; j < (N_ / 4) / 256; j++) {
            float4 v = xr[tid + j * 256];
            sum += (v.x + v.y) + (v.z + v.w);
        }
        #pragma unroll
        for (int off = 16; off > 0; off >>= 1)
            sum += __shfl_xor_sync(0xffffffffu, sum, off);

        __shared__ float wsum[8];
        const int lane = tid & 31;
        const int wid  = tid >> 5;
        if (lane == 0) wsum[wid] = sum;
        __syncthreads();
        if (wid == 0) {
            float s = (lane < 8) ? wsum[lane] : 0.0f;
            #pragma unroll
            for (int off = 4; off > 0; off >>= 1)
                s += __shfl_xor_sync(0xffffffffu, s, off);
            if (lane == 0) g_S[row] = s;
        }
        __syncthreads();   // all reader stores precede tid0's release ticket
    } else {
        // ------------------- WRITER: pure zero stores ----------------------
        const int wblk = idx2;             // 0..2047
        float4 z = make_float4(0.0f, 0.0f, 0.0f, 0.0f);
        float4* o4 = reinterpret_cast<float4*>(out) + (size_t)wblk * W4_MAIN;
        #pragma unroll
        for (int j = 0; j < W4_MAIN / 256; j++)
            __stcs(&o4[tid + j * 256], z);
        if (wblk == 0) {
            float4* orem = reinterpret_cast<float4*>(out) + (size_t)NROWS * W4_MAIN;
            #pragma unroll
            for (int j = 0; j < W4_REM / 256; j++)
                __stcs(&orem[tid + j * 256], z);
        }
        __syncthreads();   // all writer stores precede tid0's release ticket
    }

    // ----------------------- ticket + head tail ----------------------------
    __shared__ unsigned ts;
    if (tid == 0) ts = ticket_release(&g_ctr);
    __syncthreads();
    const unsigned t    = ts;
    const unsigned r    = t & (unsigned)(NBLK - 1);
    const unsigned base = t - r;

    if (r >= (unsigned)(NBLK - B_)) {      // last 16 arrivals -> head work
        if (tid == 0) {
            while (load_acquire(&g_ctr) - base < (unsigned)NBLK) { }
        }
        __syncthreads();                   // acquire propagates block-wide

        const int b = (int)(r - (unsigned)(NBLK - B_));   // 0..15

        __shared__ float Ssh[CIN_];
        __shared__ float part[256];
        if (tid < CIN_) Ssh[tid] = g_S[b * CIN_ + tid];
        __syncthreads();

        const int o    = tid & (COUT_ - 1);
        const int half = tid >> 7;
        float acc = 0.0f;
        #pragma unroll 8
        for (int i = half * (CIN_ / 2); i < (half + 1) * (CIN_ / 2); i++)
            acc += Ssh[i] * g_W[i * COUT_ + o];
        part[tid] = acc;
        __syncthreads();

        if (tid < COUT_) {
            float v = (part[tid] + part[tid + COUT_]) * (1.0f / 4097.0f);
            out[(size_t)(b * COUT_ + tid) * LOUT_] = v;
        }
    }
}

// ---------------------------------------------------------------------------
extern "C" void kernel_launch(void* const* d_in, const int* in_sizes, int n_in,
                              void* d_out, int out_size) {
    const float* x = (const float*)d_in[0];
    const float* w = (const float*)d_in[1];
    float* out = (float*)d_out;

    fused_kernel<<<NBLK, 256>>>(x, w, out);
}

// round 14
// speedup vs baseline: 1.2140x; 1.1193x over previous
#include <cuda_runtime.h>

// Problem constants: x[16,128,8192] f32, weights1[128,128,2048] f32,
// output [16,128,4097] f32.
#define B_     16
#define CIN_   128
#define COUT_  128
#define N_     8192
#define MODES_ 2048
#define LOUT_  4097

#define NROWS    (B_ * CIN_)                 // 2048 reader blocks
#define NWRITERS 1024                        // writer blocks
#define NBLK     (NROWS + NWRITERS)          // 3072 total
#define OUT4     ((B_ * COUT_ * LOUT_) / 4)  // 2097664 float4
#define W4_MAIN  2048                        // float4 per writer (32KB)
#define W4_REM   (OUT4 - NWRITERS * W4_MAIN) // 512 remainder float4 (no head elems)

// Head accumulators, zero-init at load; each replay's finishers reset to 0.
__device__ float g_acc[B_ * COUT_];
// Per-batch monotonic tickets (never reset; 128 arrivals/replay, wrap-safe).
__device__ unsigned g_ctr_b[B_];

__device__ __forceinline__ unsigned ticket_acq_rel(unsigned* p) {
    unsigned t;
    asm volatile("atom.add.acq_rel.gpu.global.u32 %0, [%1], 1;"
                 : "=r"(t) : "l"(p) : "memory");
    return t;
}
__device__ __forceinline__ float ld_cg(const float* p) {
    float v;
    asm volatile("ld.global.cg.f32 %0, [%1];" : "=f"(v) : "l"(p) : "memory");
    return v;
}

// ---------------------------------------------------------------------------
// Single kernel, no global barrier. Groups of 3 blocks = 2 readers + 1 writer
// (interleaved so read/write DRAM streams mix evenly across the wave).
//
// READER (row = b*128+i):
//   tid<128 prefetches wv = w[i,tid,0]; block row-sums x[row] -> S;
//   tid<128: atomicAdd(g_acc[b*128+tid], S*wv); acq_rel ticket on g_ctr_b[b].
//   The 128th arrival (finisher) reads g_acc, writes out[b,o,0] (scaled),
//   and resets g_acc to 0 for the next graph replay.
// WRITER (g): zero-stores 32KB slice of out, skipping the <=2 head elements
//   (element index r*4097) inside its slice; writer 0 also does the 2KB
//   remainder (which contains no head elements). No ticket, just exit.
// ---------------------------------------------------------------------------
__global__ void __launch_bounds__(256) fused_kernel(const float* __restrict__ x,
                                                    const float* __restrict__ w,
                                                    float* __restrict__ out) {
    const int blk = blockIdx.x;            // 0..3071
    const int tid = threadIdx.x;
    const int grp = blk / 3;
    const int sub = blk - grp * 3;

    if (sub < 2) {
        // ------------------------------ READER -----------------------------
        const int row = grp * 2 + sub;     // 0..2047
        const int b   = row >> 7;
        const int i   = row & (CIN_ - 1);

        // prefetch head weight for this (i, o=tid) early to hide latency
        float wv = 0.0f;
        if (tid < COUT_)
            wv = __ldg(&w[(size_t)(i * COUT_ + tid) * MODES_]);

        const float4* __restrict__ xr =
            reinterpret_cast<const float4*>(x) + (size_t)row * (N_ / 4);
        float sum = 0.0f;
        #pragma unroll
        for (int j = 0; j < (N_ / 4) / 256; j++) {
            float4 v = xr[tid + j * 256];
            sum += (v.x + v.y) + (v.z + v.w);
        }
        #pragma unroll
        for (int off = 16; off > 0; off >>= 1)
            sum += __shfl_xor_sync(0xffffffffu, sum, off);

        __shared__ float wsum[8];
        __shared__ float Sb;
        const int lane = tid & 31;
        const int wid  = tid >> 5;
        if (lane == 0) wsum[wid] = sum;
        __syncthreads();
        if (wid == 0) {
            float s = (lane < 8) ? wsum[lane] : 0.0f;
            #pragma unroll
            for (int off = 4; off > 0; off >>= 1)
                s += __shfl_xor_sync(0xffffffffu, s, off);
            if (lane == 0) Sb = s;
        }
        __syncthreads();
        const float S = Sb;

        if (tid < COUT_)
            atomicAdd(&g_acc[b * COUT_ + tid], S * wv);
        __syncthreads();                   // all atomics issued before ticket

        __shared__ unsigned ts;
        if (tid == 0) ts = ticket_acq_rel(&g_ctr_b[b]);
        __syncthreads();
        const unsigned rank = ts & (unsigned)(CIN_ - 1);

        if (rank == (unsigned)(CIN_ - 1)) {
            // finisher: acq_rel RMW saw all 127 prior releases; syncthreads
            // propagated that acquire block-wide.
            if (tid < COUT_) {
                float a = ld_cg(&g_acc[b * COUT_ + tid]);
                out[(size_t)(b * COUT_ + tid) * LOUT_] = a * (1.0f / 4097.0f);
                g_acc[b * COUT_ + tid] = 0.0f;   // reset for next replay
            }
        }
    } else {
        // ------------------------------ WRITER -----------------------------
        const int g = grp;                 // 0..1023
        const long long e0 = (long long)g * (W4_MAIN * 4);       // first element
        const long long e1 = e0 + W4_MAIN * 4;                   // end element
        // head rows r with r*4097 in [e0, e1): r_lo = ceil(e0/4097), <=2 of them
        const int r_lo = (int)((e0 + LOUT_ - 1) / LOUT_);
        int sp0 = -1, sp1 = -1;            // element offsets within slice
        if (r_lo < NROWS && (long long)r_lo * LOUT_ < e1)
            sp0 = (int)((long long)r_lo * LOUT_ - e0);
        if (r_lo + 1 < NROWS && (long long)(r_lo + 1) * LOUT_ < e1)
            sp1 = (int)((long long)(r_lo + 1) * LOUT_ - e0);
        const int sp0f4 = sp0 >> 2, sp1f4 = sp1 >> 2;

        float4 z = make_float4(0.0f, 0.0f, 0.0f, 0.0f);
        float4* o4 = reinterpret_cast<float4*>(out) + (size_t)g * W4_MAIN;
        #pragma unroll
        for (int j = 0; j < W4_MAIN / 256; j++) {
            const int idx = tid + j * 256;
            if (idx != sp0f4 && idx != sp1f4) {
                __stcs(&o4[idx], z);
            } else {
                const int sc = (idx == sp0f4) ? (sp0 & 3) : (sp1 & 3);
                float* os = reinterpret_cast<float*>(o4 + idx);
                #pragma unroll
                for (int c = 0; c < 4; c++)
                    if (c != sc) __stcs(&os[c], 0.0f);
            }
        }
        if (g == 0) {
            // remainder: elements [NWRITERS*8192, OUT4*4) — contains no head
            // elements (max head elem 2047*4097 < 1024*8192).
            float4* orem = reinterpret_cast<float4*>(out) + (size_t)NWRITERS * W4_MAIN;
            #pragma unroll
            for (int j = 0; j < W4_REM / 256; j++)
                __stcs(&orem[tid + j * 256], z);
        }
    }
}

// ---------------------------------------------------------------------------
extern "C" void kernel_launch(void* const* d_in, const int* in_sizes, int n_in,
                              void* d_out, int out_size) {
    const float* x = (const float*)d_in[0];
    const float* w = (const float*)d_in[1];
    float* out = (float*)d_out;

    fused_kernel<<<NBLK, 256>>>(x, w, out);
}

// round 15
// speedup vs baseline: 1.3844x; 1.1404x over previous
#include <cuda_runtime.h>

// Problem constants: x[16,128,8192] f32, weights1[128,128,2048] f32,
// output [16,128,4097] f32.
#define B_     16
#define CIN_   128
#define COUT_  128
#define N_     8192
#define MODES_ 2048
#define LOUT_  4097

#define NROWS    (B_ * CIN_)                 // 2048 reader rows
#define NBLK     1024                        // single-wave persistent grid
#define OUT4     ((B_ * COUT_ * LOUT_) / 4)  // 2097664 float4
#define W4_MAIN  2048                        // float4 per writer slice (32KB)
#define W4_REM   (OUT4 - NBLK * W4_MAIN)     // 512 remainder float4 (no head elems)

// Head accumulators, zero-init at load; each replay's finishers reset to 0.
__device__ float g_acc[B_ * COUT_];
// Per-batch monotonic tickets (64 arrivals/replay, power of 2 -> wrap-safe).
__device__ unsigned g_ctr_b[B_];

__device__ __forceinline__ unsigned ticket_acq_rel(unsigned* p) {
    unsigned t;
    asm volatile("atom.add.acq_rel.gpu.global.u32 %0, [%1], 1;"
                 : "=r"(t) : "l"(p) : "memory");
    return t;
}
__device__ __forceinline__ float ld_cg(const float* p) {
    float v;
    asm volatile("ld.global.cg.f32 %0, [%1];" : "=f"(v) : "l"(p) : "memory");
    return v;
}

// ---------------------------------------------------------------------------
// Single-wave kernel: 1024 blocks, each block g does (in order):
//   1. WRITER: evict-first zero stores of out slice [g*8192, (g+1)*8192)
//      elements, skipping the <=2 head elements (index r*4097) inside it;
//      block 0 also zeroes the 2KB remainder (contains no head elements).
//      Stores are fire-and-forget -> stream out while reads proceed.
//   2. DUAL READER: rows 2g and 2g+1 (same b, i and i+1). Interleaved loads
//      of both rows (16-deep MLP), two shuffle reductions -> S0, S1.
//   3. HEAD: tid<128 does ONE atomicAdd of S0*w[i0,o,0] + S1*w[i1,o,0].
//      Per-b acq_rel ticket; 64th arrival writes out[b,o,0] (scaled) from
//      g_acc and resets g_acc to 0 for the next graph replay.
// ---------------------------------------------------------------------------
__global__ void __launch_bounds__(256) fused_kernel(const float* __restrict__ x,
                                                    const float* __restrict__ w,
                                                    float* __restrict__ out) {
    const int g   = blockIdx.x;            // 0..1023
    const int tid = threadIdx.x;

    // ---- head-weight prefetch for both rows (hide latency under stores) ----
    const int row0 = 2 * g;
    const int b    = row0 >> 7;
    const int i0   = row0 & (CIN_ - 1);
    float wv0 = 0.0f, wv1 = 0.0f;
    if (tid < COUT_) {
        wv0 = __ldg(&w[(size_t)(i0 * COUT_ + tid) * MODES_]);
        wv1 = __ldg(&w[(size_t)((i0 + 1) * COUT_ + tid) * MODES_]);
    }

    // ------------------------------ WRITER ---------------------------------
    {
        const long long e0 = (long long)g * (W4_MAIN * 4);
        const long long e1 = e0 + W4_MAIN * 4;
        const int r_lo = (int)((e0 + LOUT_ - 1) / LOUT_);
        int sp0 = -1, sp1 = -1;
        if (r_lo < NROWS && (long long)r_lo * LOUT_ < e1)
            sp0 = (int)((long long)r_lo * LOUT_ - e0);
        if (r_lo + 1 < NROWS && (long long)(r_lo + 1) * LOUT_ < e1)
            sp1 = (int)((long long)(r_lo + 1) * LOUT_ - e0);
        const int sp0f4 = sp0 >> 2, sp1f4 = sp1 >> 2;

        float4 z = make_float4(0.0f, 0.0f, 0.0f, 0.0f);
        float4* o4 = reinterpret_cast<float4*>(out) + (size_t)g * W4_MAIN;
        #pragma unroll
        for (int j = 0; j < W4_MAIN / 256; j++) {
            const int idx = tid + j * 256;
            if (idx != sp0f4 && idx != sp1f4) {
                __stcs(&o4[idx], z);
            } else {
                const int sc = (idx == sp0f4) ? (sp0 & 3) : (sp1 & 3);
                float* os = reinterpret_cast<float*>(o4 + idx);
                #pragma unroll
                for (int c = 0; c < 4; c++)
                    if (c != sc) __stcs(&os[c], 0.0f);
            }
        }
        if (g == 0) {
            float4* orem = reinterpret_cast<float4*>(out) + (size_t)NBLK * W4_MAIN;
            #pragma unroll
            for (int j = 0; j < W4_REM / 256; j++)
                __stcs(&orem[tid + j * 256], z);
        }
    }

    // --------------------------- DUAL READER --------------------------------
    const float4* __restrict__ xr0 =
        reinterpret_cast<const float4*>(x) + (size_t)row0 * (N_ / 4);
    const float4* __restrict__ xr1 = xr0 + (N_ / 4);
    float sum0 = 0.0f, sum1 = 0.0f;
    #pragma unroll
    for (int j = 0; j < (N_ / 4) / 256; j++) {
        float4 v0 = xr0[tid + j * 256];
        float4 v1 = xr1[tid + j * 256];
        sum0 += (v0.x + v0.y) + (v0.z + v0.w);
        sum1 += (v1.x + v1.y) + (v1.z + v1.w);
    }
    #pragma unroll
    for (int off = 16; off > 0; off >>= 1) {
        sum0 += __shfl_xor_sync(0xffffffffu, sum0, off);
        sum1 += __shfl_xor_sync(0xffffffffu, sum1, off);
    }

    __shared__ float2 wsum[8];
    __shared__ float2 Sb;
    const int lane = tid & 31;
    const int wid  = tid >> 5;
    if (lane == 0) wsum[wid] = make_float2(sum0, sum1);
    __syncthreads();
    if (wid == 0) {
        float2 sv = (lane < 8) ? wsum[lane] : make_float2(0.0f, 0.0f);
        float s0 = sv.x, s1 = sv.y;
        #pragma unroll
        for (int off = 4; off > 0; off >>= 1) {
            s0 += __shfl_xor_sync(0xffffffffu, s0, off);
            s1 += __shfl_xor_sync(0xffffffffu, s1, off);
        }
        if (lane == 0) Sb = make_float2(s0, s1);
    }
    __syncthreads();
    const float S0 = Sb.x, S1 = Sb.y;

    // ------------------------------- HEAD -----------------------------------
    if (tid < COUT_)
        atomicAdd(&g_acc[b * COUT_ + tid], S0 * wv0 + S1 * wv1);
    __syncthreads();                       // atomics issued before ticket

    __shared__ unsigned ts;
    if (tid == 0) ts = ticket_acq_rel(&g_ctr_b[b]);
    __syncthreads();
    const unsigned rank = ts & 63u;        // 64 pair-arrivals per b per replay

    if (rank == 63u) {
        // finisher: acq_rel RMW saw all prior releases for this b.
        if (tid < COUT_) {
            float a = ld_cg(&g_acc[b * COUT_ + tid]);
            out[(size_t)(b * COUT_ + tid) * LOUT_] = a * (1.0f / 4097.0f);
            g_acc[b * COUT_ + tid] = 0.0f; // reset for next replay
        }
    }
}

// ---------------------------------------------------------------------------
extern "C" void kernel_launch(void* const* d_in, const int* in_sizes, int n_in,
                              void* d_out, int out_size) {
    const float* x = (const float*)d_in[0];
    const float* w = (const float*)d_in[1];
    float* out = (float*)d_out;

    fused_kernel<<<NBLK, 256>>>(x, w, out);
}